// round 8
// baseline (speedup 1.0000x reference)
#include <cuda_runtime.h>
#include <cuda_bf16.h>

// 4-qubit circuit, algebraically collapsed:
//   embedded state v = kron of per-wire (cos,sin)  (real)
//   entangling block = fixed 16x16 complex unitary U (weights only)
//   z_w = sign-tree over |U v|^2
//
// R8 = R7 with the grid-size bug fixed: each warp covers 32 samples
// (16 lane pairs x 2), so the grid is B/128 = 2048 blocks (R7 launched 1024
// -> half the outputs were poison, rel_err 0.707).
// Lane-pair split: lanes (l, l+16) cooperate on the same 2 samples; each
// thread owns 8 of 16 output rows -> 32 accumulator regs, 64 LDS/thread,
// readout partials merged with shfl_xor(16).

#define N_QUBITS 4
#define N_LAYERS 6
#define N_AMPS   16
#define THREADS  128
#define U_F4     128        // 16x16 complex = 256 float2 = 128 x 16B slots

__device__ float4 g_U[U_F4];   // col i: float2 slots [i*16, i*16+16); m-th = U[m][i]

// ---------------- init: evolve 16 basis columns, shfl pair-exchange ----------------
__global__ void init_u_kernel(const float* __restrict__ w) {
    __shared__ float4 gm[N_LAYERS * N_QUBITS][2];
    int t = threadIdx.x;
    if (t < N_LAYERS * N_QUBITS) {
        float phi   = w[t * 3 + 0];
        float theta = w[t * 3 + 1];
        float omega = w[t * 3 + 2];
        float st, ct, sp, cp, sm, cm;
        __sincosf(theta * 0.5f, &st, &ct);
        __sincosf((phi + omega) * 0.5f, &sp, &cp);
        __sincosf((phi - omega) * 0.5f, &sm, &cm);
        gm[t][0] = make_float4( cp * ct, -sp * ct,   // u00
                               -cm * st, -sm * st);  // u01
        gm[t][1] = make_float4( cm * st, -sm * st,   // u10
                                cp * ct,  sp * ct);  // u11
    }
    __syncthreads();

    // 256 threads = 8 warps; each warp evolves 2 columns (16 lanes each).
    int lane   = t & 31;
    int lane16 = lane & 15;
    int col    = (t >> 5) * 2 + (lane >> 4);
    float re = (lane16 == col) ? 1.0f : 0.0f;
    float im = 0.0f;

    #pragma unroll
    for (int l = 0; l < N_LAYERS; l++) {
        #pragma unroll
        for (int q = 0; q < N_QUBITS; q++) {
            int idx = l * N_QUBITS + q;
            float4 row0 = gm[idx][0];
            float4 row1 = gm[idx][1];
            const int stride = 8 >> q;
            int bit = lane16 & stride;
            float pre = __shfl_xor_sync(0xffffffffu, re, stride);
            float pim = __shfl_xor_sync(0xffffffffu, im, stride);
            float c0r = bit ? row1.x : row0.x,  c0i = bit ? row1.y : row0.y;
            float c1r = bit ? row1.z : row0.z,  c1i = bit ? row1.w : row0.w;
            float a0r = bit ? pre : re,  a0i = bit ? pim : im;
            float a1r = bit ? re : pre,  a1i = bit ? im : pim;
            float nre = c0r * a0r - c0i * a0i + c1r * a1r - c1i * a1i;
            float nim = c0r * a0i + c0i * a0r + c1r * a1i + c1i * a1r;
            re = nre; im = nim;
        }
        const int r = l % (N_QUBITS - 1) + 1;
        #pragma unroll
        for (int q = 0; q < N_QUBITS; q++) {
            const int cbit = 8 >> q, tbit = 8 >> ((q + r) % N_QUBITS);
            float pre = __shfl_xor_sync(0xffffffffu, re, tbit);
            float pim = __shfl_xor_sync(0xffffffffu, im, tbit);
            bool flip = (lane16 & cbit) != 0;
            re = flip ? pre : re;
            im = flip ? pim : im;
        }
    }
    float2* U = reinterpret_cast<float2*>(g_U);
    U[col * N_AMPS + lane16] = make_float2(re, im);
}

// ---------------- main ----------------
__device__ __forceinline__ unsigned long long pack2(float lo, float hi) {
    unsigned long long r;
    asm("mov.b64 %0, {%1, %2};" : "=l"(r) : "f"(lo), "f"(hi));
    return r;
}

__device__ __forceinline__ void embed_pq(const float4 x, float* P, float* Q) {
    float c0, s0, c1, s1, c2, s2, c3, s3;
    __sincosf(x.x * 0.5f, &s0, &c0);
    __sincosf(x.y * 0.5f, &s1, &c1);
    __sincosf(x.z * 0.5f, &s2, &c2);
    __sincosf(x.w * 0.5f, &s3, &c3);
    P[0] = c0 * c1; P[1] = c0 * s1; P[2] = s0 * c1; P[3] = s0 * s1;
    Q[0] = c2 * c3; Q[1] = c2 * s3; Q[2] = s2 * c3; Q[3] = s2 * s3;
}

// partial z (4 values) from this thread's 8 rows; rh gives the z0 sign
__device__ __forceinline__ float4 partial_z(const unsigned long long* y, int rh) {
    float p[8];
    #pragma unroll
    for (int r = 0; r < 8; r++) {
        float re, im;
        asm("mov.b64 {%0, %1}, %2;" : "=f"(re), "=f"(im) : "l"(y[r]));
        p[r] = re * re + im * im;
    }
    float z3 = ((p[0] - p[1]) + (p[2] - p[3])) + ((p[4] - p[5]) + (p[6] - p[7]));
    float a0 = p[0] + p[1], a1 = p[2] + p[3], a2 = p[4] + p[5], a3 = p[6] + p[7];
    float z2 = (a0 - a1) + (a2 - a3);
    float b0 = a0 + a1, b1 = a2 + a3;
    float z1 = b0 - b1;
    float tot = b0 + b1;
    float z0 = rh ? -tot : tot;
    return make_float4(z0, z1, z2, z3);
}

__global__ void __launch_bounds__(THREADS, 5)
quantum_main_kernel(const float* __restrict__ inputs,
                    float* __restrict__ out) {
    __shared__ float4 sU[U_F4];
    sU[threadIdx.x] = g_U[threadIdx.x];     // THREADS == U_F4
    __syncthreads();

    const int lane = threadIdx.x & 31;
    const int rh   = lane >> 4;             // row half: 0 -> rows 0..7, 1 -> rows 8..15
    const int pair = lane & 15;
    const int gw   = (blockIdx.x * THREADS + threadIdx.x) >> 5;   // global warp id
    const int s0   = gw * 32 + pair * 2;    // this pair's two samples
    const int s1   = s0 + 1;

    // this thread's half of U: rows [8rh, 8rh+8) = 4 ulonglong2 slots per column
    const ulonglong2* sUh = reinterpret_cast<const ulonglong2*>(sU) + rh * 4;

    const float4* in4 = reinterpret_cast<const float4*>(inputs);
    float P0[4], Q0[4], P1[4], Q1[4];
    embed_pq(__ldg(in4 + s0), P0, Q0);
    embed_pq(__ldg(in4 + s1), P1, Q1);

    unsigned long long y0[8], y1[8];        // 8 rows x 2 samples

    // ---- i = 0: init accumulators with packed MUL ----
    {
        float va = P0[0] * Q0[0];
        float vb = P1[0] * Q1[0];
        unsigned long long vp0 = pack2(va, va);
        unsigned long long vp1 = pack2(vb, vb);
        #pragma unroll
        for (int j = 0; j < 4; j++) {
            ulonglong2 uu = sUh[j];
            asm("mul.rn.f32x2 %0, %1, %2;" : "=l"(y0[2*j    ]) : "l"(uu.x), "l"(vp0));
            asm("mul.rn.f32x2 %0, %1, %2;" : "=l"(y0[2*j + 1]) : "l"(uu.y), "l"(vp0));
            asm("mul.rn.f32x2 %0, %1, %2;" : "=l"(y1[2*j    ]) : "l"(uu.x), "l"(vp1));
            asm("mul.rn.f32x2 %0, %1, %2;" : "=l"(y1[2*j + 1]) : "l"(uu.y), "l"(vp1));
        }
    }

    // ---- i = 1..15: packed FFMA accumulate over columns ----
    #pragma unroll
    for (int i = 1; i < N_AMPS; i++) {
        float va = P0[i >> 2] * Q0[i & 3];
        float vb = P1[i >> 2] * Q1[i & 3];
        unsigned long long vp0 = pack2(va, va);
        unsigned long long vp1 = pack2(vb, vb);
        #pragma unroll
        for (int j = 0; j < 4; j++) {
            ulonglong2 uu = sUh[i * 8 + j];
            asm("fma.rn.f32x2 %0, %1, %2, %0;" : "+l"(y0[2*j    ]) : "l"(uu.x), "l"(vp0));
            asm("fma.rn.f32x2 %0, %1, %2, %0;" : "+l"(y0[2*j + 1]) : "l"(uu.y), "l"(vp0));
            asm("fma.rn.f32x2 %0, %1, %2, %0;" : "+l"(y1[2*j    ]) : "l"(uu.x), "l"(vp1));
            asm("fma.rn.f32x2 %0, %1, %2, %0;" : "+l"(y1[2*j + 1]) : "l"(uu.y), "l"(vp1));
        }
    }

    // ---- readout: combine row-half partials across the lane pair ----
    float4 zp0 = partial_z(y0, rh);
    float4 zp1 = partial_z(y1, rh);
    float4 z0f, z1f;
    z0f.x = zp0.x + __shfl_xor_sync(0xffffffffu, zp0.x, 16);
    z0f.y = zp0.y + __shfl_xor_sync(0xffffffffu, zp0.y, 16);
    z0f.z = zp0.z + __shfl_xor_sync(0xffffffffu, zp0.z, 16);
    z0f.w = zp0.w + __shfl_xor_sync(0xffffffffu, zp0.w, 16);
    z1f.x = zp1.x + __shfl_xor_sync(0xffffffffu, zp1.x, 16);
    z1f.y = zp1.y + __shfl_xor_sync(0xffffffffu, zp1.y, 16);
    z1f.z = zp1.z + __shfl_xor_sync(0xffffffffu, zp1.z, 16);
    z1f.w = zp1.w + __shfl_xor_sync(0xffffffffu, zp1.w, 16);

    // lane<16 writes sample s0, partner writes s1 (both hold identical sums)
    float4* out4 = reinterpret_cast<float4*>(out);
    out4[rh ? s1 : s0] = rh ? z1f : z0f;
}

extern "C" void kernel_launch(void* const* d_in, const int* in_sizes, int n_in,
                              void* d_out, int out_size) {
    const float* inputs  = (const float*)d_in[0];   // (B, 4) float32
    const float* weights = (const float*)d_in[1];   // (6, 4, 3) float32
    float* out = (float*)d_out;                     // (B, 4) float32
    int B = in_sizes[0] / N_QUBITS;

    init_u_kernel<<<1, 256>>>(weights);
    // each warp covers 32 samples (16 lane pairs x 2) -> B/128 blocks of 128
    int blocks = B / THREADS;                       // 262144 / 128 = 2048
    quantum_main_kernel<<<blocks, THREADS>>>(inputs, out);
}